// round 6
// baseline (speedup 1.0000x reference)
#include <cuda_runtime.h>

// ---------------------------------------------------------------------------
// Elman RNN (relu), B=64, T=512, I=64, H=1024, O=64
// out = [ hidden_list (B,T,H) | output_list (B,T,O) | h_last (1,B,H) ]
// ---------------------------------------------------------------------------

#define B_   64
#define T_   512
#define I_   64
#define H_   1024
#define O_   64

#define HID_OFF  0
#define OUT_OFF  (B_ * T_ * H_)              // 33554432
#define HL_OFF   (OUT_OFF + B_ * T_ * O_)    // 35651584

#define NBLK 128        // persistent blocks (1/SM)
#define TB   256        // 8 warps; warps 0-3 = batch rows 0-7, 4-7 = rows 8-15

// SMEM layout (floats): 32 K-chunks of 32 floats, each padded to 34
#define CH    34
#define HRow  1088      // 32 * 34

// scratch: h double buffer + per-(group,block) flags (128B stride, no atomics)
__device__ float    g_hbuf[2][B_ * H_];
__device__ unsigned g_flag[4][32][32];      // [batch group][col group][pad]

typedef unsigned long long ull;

__device__ __forceinline__ ull f2fma(ull a, ull b, ull c) {
    ull d;
    asm("fma.rn.f32x2 %0, %1, %2, %3;" : "=l"(d) : "l"(a), "l"(b), "l"(c));
    return d;
}
__device__ __forceinline__ float pairsum(ull a) {
    float lo = __uint_as_float((unsigned)(a & 0xffffffffull));
    float hi = __uint_as_float((unsigned)(a >> 32));
    return lo + hi;
}
__device__ __forceinline__ unsigned ld_acq(unsigned* p) {
    unsigned v;
    asm volatile("ld.acquire.gpu.u32 %0, [%1];" : "=r"(v) : "l"(p) : "memory");
    return v;
}
__device__ __forceinline__ void st_rel(unsigned* p, unsigned v) {
    asm volatile("st.release.gpu.u32 [%0], %1;" :: "l"(p), "r"(v) : "memory");
}

// ---------------------------------------------------------------------------
// Kernel R: zero the flag array (graph-replay determinism)
// ---------------------------------------------------------------------------
__global__ void reset_flags() {
    ((unsigned*)g_flag)[blockIdx.x * blockDim.x + threadIdx.x] = 0;
}

// ---------------------------------------------------------------------------
// Kernel A: xw[bt][h] = x[bt]·W_ih[h] + b_ih[h] + b_hh[h]  -> hidden region
// ---------------------------------------------------------------------------
__global__ void __launch_bounds__(256) xw_kernel(
    const float* __restrict__ x, const float* __restrict__ Wih,
    const float* __restrict__ bih, const float* __restrict__ bhh,
    float* __restrict__ hid_out)
{
    __shared__ float xs[64 * 65];
    __shared__ float ws[64 * 65];

    const int tid = threadIdx.x;
    const int hb  = blockIdx.x * 64;
    const int btb = blockIdx.y * 64;

    #pragma unroll
    for (int i = tid; i < 64 * 64; i += 256) {
        int r = i >> 6, c = i & 63;
        xs[r * 65 + c] = x[(btb + r) * 64 + c];
        ws[r * 65 + c] = Wih[(hb + r) * 64 + c];
    }
    __syncthreads();

    const int tx = tid & 15, ty = tid >> 4;
    float acc[4][4] = {};

    #pragma unroll 8
    for (int k = 0; k < 64; ++k) {
        float a0 = xs[(ty     ) * 65 + k];
        float a1 = xs[(ty + 16) * 65 + k];
        float a2 = xs[(ty + 32) * 65 + k];
        float a3 = xs[(ty + 48) * 65 + k];
        float b0 = ws[(tx     ) * 65 + k];
        float b1 = ws[(tx + 16) * 65 + k];
        float b2 = ws[(tx + 32) * 65 + k];
        float b3 = ws[(tx + 48) * 65 + k];
        acc[0][0] += a0 * b0; acc[0][1] += a0 * b1; acc[0][2] += a0 * b2; acc[0][3] += a0 * b3;
        acc[1][0] += a1 * b0; acc[1][1] += a1 * b1; acc[1][2] += a1 * b2; acc[1][3] += a1 * b3;
        acc[2][0] += a2 * b0; acc[2][1] += a2 * b1; acc[2][2] += a2 * b2; acc[2][3] += a2 * b3;
        acc[3][0] += a3 * b0; acc[3][1] += a3 * b1; acc[3][2] += a3 * b2; acc[3][3] += a3 * b3;
    }

    #pragma unroll
    for (int j = 0; j < 4; ++j) {
        int h = hb + tx + 16 * j;
        float bb = bih[h] + bhh[h];
        #pragma unroll
        for (int i = 0; i < 4; ++i) {
            int bt = btb + ty + 16 * i;
            hid_out[bt * H_ + h] = acc[i][j] + bb;
        }
    }
}

// ---------------------------------------------------------------------------
// Kernel B: persistent recurrence, phase-split by batch-half.
// 128 blocks = 4 batch-groups(16) x 32 col-groups(32).
// Warp w: pm = w>>2 (batch half), pn = w&3 (col octet); lane = K-chunk kc.
// Step: wait flags -> stage rows 0..7 (all) -> phase A (warps 0-3 FMA)
// concurrent with stage rows 8..15 (warps 4-7) -> phase B (warps 4-7 FMA)
// concurrent with warps 0-3 reduction/epilogue -> flag release.
// ---------------------------------------------------------------------------
__global__ void __launch_bounds__(TB, 1) rnn_recur(
    const float* __restrict__ hid_in,
    const float* __restrict__ Whh,
    float* __restrict__ out)
{
    extern __shared__ float sm[];
    float* wsm = sm;                 // 32 rows x HRow  (~136 KB)
    float* hsm = sm + 32 * HRow;     // 16 rows x HRow  (~68 KB)

    const int tid = threadIdx.x;
    const int bi  = blockIdx.x >> 5;
    const int ci  = blockIdx.x & 31;
    const int b0  = bi * 16;
    const int c0  = ci * 32;

    const int lane = tid & 31;
    const int w    = tid >> 5;
    const int pm   = w >> 2;           // batch half (SMSP = w&3 in both halves)
    const int pn   = w & 3;            // col octet
    const int kc   = lane;             // K-chunk of 32 floats

    // ---- stage W_hh slice once: rows c0..c0+31, chunked layout ----
    const float2* W2 = (const float2*)Whh;
    #pragma unroll 4
    for (int i = tid; i < 32 * 512; i += TB) {
        int r = i >> 9, q = i & 511;
        *(float2*)&wsm[r * HRow + (q >> 4) * CH + (q & 15) * 2] =
            __ldg(&W2[(c0 + r) * 512 + q]);
    }

    const float* hb_ = hsm + pm * 8 * HRow + kc * CH;
    const float* wb_ = wsm + pn * 8 * HRow + kc * CH;

    float* hid_out = out + HID_OFF;
    float* hlast   = out + HL_OFF;

    // post-shuffle epilogue mapping: lane holds outputs
    // (batch pm*8 + (lane>>2), cols pn*8 + 2*(lane&3) + {0,1})
    const int gb = b0 + pm * 8 + (lane >> 2);
    const int gc = c0 + pn * 8 + 2 * (lane & 3);

    #pragma unroll 1
    for (int s = 0; s < T_; ++s) {
        // prefetch xw for this thread's two outputs (own location, safe early)
        float2 xw = *(const float2*)&hid_out[((size_t)gb * T_ + s) * H_ + gc];

        // ---- wait: warp 0 polls all 32 producer flags in parallel ----
        if (s > 0) {
            if (tid < 32)
                while ((int)(ld_acq(&g_flag[bi][tid][0]) - (unsigned)s) < 0) { }
            __syncthreads();   // also fences prev-step hsm reads vs restaging
        }

        const float2* hsrc = (s == 0) ? (const float2*)hid_in
                                      : (const float2*)g_hbuf[(s - 1) & 1];

        // ---- stage rows 0..7 (half A) by all 256 threads ----
        #pragma unroll 8
        for (int t = 0; t < 16; ++t) {
            int i = t * 256 + tid;
            int r = i >> 9, q = i & 511;
            *(float2*)&hsm[r * HRow + (q >> 4) * CH + (q & 15) * 2] =
                __ldcg(&hsrc[(b0 + r) * 512 + q]);
        }
        __syncthreads();

        if (pm == 1) {
            // ---- stage rows 8..15 (half B) by warps 4..7 ----
            const int tid2 = tid - 128;
            #pragma unroll 8
            for (int t = 0; t < 32; ++t) {
                int i = t * 128 + tid2;
                int r = 8 + (i >> 9), q = i & 511;
                *(float2*)&hsm[r * HRow + (q >> 4) * CH + (q & 15) * 2] =
                    __ldcg(&hsrc[(b0 + r) * 512 + q]);
            }
            asm volatile("bar.sync 1, 128;" ::: "memory");
        }

        // ---- 8x8 tile over private K-chunk of 32 (each warp, its half) ----
        ull acc[64];
        #pragma unroll
        for (int i = 0; i < 64; ++i) acc[i] = 0ull;

        #pragma unroll
        for (int k2 = 0; k2 < 16; ++k2) {
            ull hv[8];
            #pragma unroll
            for (int i = 0; i < 8; ++i)
                hv[i] = *(const ull*)(hb_ + i * HRow + k2 * 2);
            ull wv[4];
            #pragma unroll
            for (int j = 0; j < 4; ++j)
                wv[j] = *(const ull*)(wb_ + j * HRow + k2 * 2);
            #pragma unroll
            for (int i = 0; i < 8; ++i)
                #pragma unroll
                for (int j = 0; j < 4; ++j)
                    acc[i * 8 + j] = f2fma(hv[i], wv[j], acc[i * 8 + j]);
            #pragma unroll
            for (int j = 0; j < 4; ++j)
                wv[j] = *(const ull*)(wb_ + (j + 4) * HRow + k2 * 2);
            #pragma unroll
            for (int i = 0; i < 8; ++i)
                #pragma unroll
                for (int j = 0; j < 4; ++j)
                    acc[i * 8 + j + 4] = f2fma(hv[i], wv[j], acc[i * 8 + j + 4]);
        }

        // ---- pairsum then 5-round butterfly shuffle reduction ----
        float vals[64];
        #pragma unroll
        for (int v = 0; v < 64; ++v) vals[v] = pairsum(acc[v]);

        #pragma unroll
        for (int m = 16, cnt = 32; m >= 1; m >>= 1, cnt >>= 1) {
            bool up = (lane & m) != 0;
            #pragma unroll
            for (int i = 0; i < 32; ++i) {
                if (i >= cnt) break;
                float send = up ? vals[i] : vals[i + cnt];
                float keep = up ? vals[i + cnt] : vals[i];
                float recv = __shfl_xor_sync(0xffffffffu, send, m);
                vals[i] = keep + recv;
            }
        }

        float2 rr;
        rr.x = fmaxf(xw.x + vals[0], 0.0f);
        rr.y = fmaxf(xw.y + vals[1], 0.0f);

        *(float2*)&hid_out[((size_t)gb * T_ + s) * H_ + gc] = rr;
        *(float2*)&g_hbuf[s & 1][gb * H_ + gc] = rr;
        if (s == T_ - 1)
            *(float2*)&hlast[gb * H_ + gc] = rr;

        // ---- publish: release own flag after all epilogues ----
        if (s != T_ - 1) {
            __syncthreads();
            if (tid == 0)
                st_rel(&g_flag[bi][ci][0], (unsigned)(s + 1));
        }
    }
}

// ---------------------------------------------------------------------------
// Kernel C: output_list[bt][o] = hid[bt]·W_out[o] + b_out[o]   (f32x2)
// ---------------------------------------------------------------------------
__global__ void __launch_bounds__(256) out_kernel(
    const float* __restrict__ hid, const float* __restrict__ Wout,
    const float* __restrict__ bout, float* __restrict__ outp)
{
    __shared__ float hs[128 * CH];
    __shared__ float ws2[64 * CH];

    const int tid = threadIdx.x;
    const int btb = blockIdx.x * 128;
    const int tx = tid & 15, ty = tid >> 4;

    const float2* hid2  = (const float2*)hid;
    const float2* wout2 = (const float2*)Wout;

    ull acc[8][4];
    #pragma unroll
    for (int i = 0; i < 8; ++i)
        #pragma unroll
        for (int j = 0; j < 4; ++j) acc[i][j] = 0ull;

    for (int kcb = 0; kcb < 512; kcb += 16) {
        #pragma unroll
        for (int i = tid; i < 128 * 16; i += 256) {
            int r = i >> 4, q = i & 15;
            *(float2*)&hs[r * CH + q * 2] = hid2[(btb + r) * 512 + kcb + q];
        }
        #pragma unroll
        for (int i = tid; i < 64 * 16; i += 256) {
            int r = i >> 4, q = i & 15;
            *(float2*)&ws2[r * CH + q * 2] = wout2[r * 512 + kcb + q];
        }
        __syncthreads();

        #pragma unroll
        for (int k2 = 0; k2 < 16; ++k2) {
            ull a[8], b[4];
            #pragma unroll
            for (int i = 0; i < 8; ++i)
                a[i] = *(const ull*)&hs[(ty + 16 * i) * CH + k2 * 2];
            #pragma unroll
            for (int j = 0; j < 4; ++j)
                b[j] = *(const ull*)&ws2[(tx + 16 * j) * CH + k2 * 2];
            #pragma unroll
            for (int i = 0; i < 8; ++i)
                #pragma unroll
                for (int j = 0; j < 4; ++j)
                    acc[i][j] = f2fma(a[i], b[j], acc[i][j]);
        }
        __syncthreads();
    }

    #pragma unroll
    for (int j = 0; j < 4; ++j) {
        int o = tx + 16 * j;
        float bb = bout[o];
        #pragma unroll
        for (int i = 0; i < 8; ++i)
            outp[(btb + ty + 16 * i) * O_ + o] = pairsum(acc[i][j]) + bb;
    }
}

// ---------------------------------------------------------------------------
extern "C" void kernel_launch(void* const* d_in, const int* in_sizes, int n_in,
                              void* d_out, int out_size) {
    const float* x      = (const float*)d_in[0];
    const float* hidden = (const float*)d_in[1];
    const float* W_ih   = (const float*)d_in[2];
    const float* W_hh   = (const float*)d_in[3];
    const float* b_ih   = (const float*)d_in[4];
    const float* b_hh   = (const float*)d_in[5];
    const float* W_out  = (const float*)d_in[6];
    const float* b_out  = (const float*)d_in[7];
    float* out = (float*)d_out;

    reset_flags<<<16, 256>>>();          // 4096 words

    dim3 gA(H_ / 64, (B_ * T_) / 64);
    xw_kernel<<<gA, 256>>>(x, W_ih, b_ih, b_hh, out + HID_OFF);

    size_t smemB = (size_t)(48 * HRow) * sizeof(float);   // 208,896 B
    cudaFuncSetAttribute(rnn_recur, cudaFuncAttributeMaxDynamicSharedMemorySize,
                         (int)smemB);
    rnn_recur<<<NBLK, TB, smemB>>>(hidden, W_hh, out);

    out_kernel<<<(B_ * T_) / 128, 256>>>(out + HID_OFF, W_out, b_out, out + OUT_OFF);
}

// round 7
// speedup vs baseline: 1.1449x; 1.1449x over previous
#include <cuda_runtime.h>

// ---------------------------------------------------------------------------
// Elman RNN (relu), B=64, T=512, I=64, H=1024, O=64
// out = [ hidden_list (B,T,H) | output_list (B,T,O) | h_last (1,B,H) ]
// ---------------------------------------------------------------------------

#define B_   64
#define T_   512
#define I_   64
#define H_   1024
#define O_   64

#define HID_OFF  0
#define OUT_OFF  (B_ * T_ * H_)              // 33554432
#define HL_OFF   (OUT_OFF + B_ * T_ * O_)    // 35651584

#define NBLK 128        // persistent blocks (1/SM)
#define TB   256        // 8 warps = 4 K-chunks x 2 col-halves

// SMEM strides (floats). 1036 mod 32 = 12 -> conflict-free row sets.
#define HS   1036
#define RED_B 161       // red batch stride (161 mod 32 = 1)
#define RED_C 5         // red col stride

// scratch: h double buffer + per-(group,block) flags (128B stride)
__device__ float    g_hbuf[2][B_ * H_];
__device__ unsigned g_flag[4][32][32];

typedef unsigned long long ull;

__device__ __forceinline__ ull f2fma(ull a, ull b, ull c) {
    ull d;
    asm("fma.rn.f32x2 %0, %1, %2, %3;" : "=l"(d) : "l"(a), "l"(b), "l"(c));
    return d;
}
__device__ __forceinline__ float pairsum(ull a) {
    float lo = __uint_as_float((unsigned)(a & 0xffffffffull));
    float hi = __uint_as_float((unsigned)(a >> 32));
    return lo + hi;
}
__device__ __forceinline__ unsigned ld_acq(unsigned* p) {
    unsigned v;
    asm volatile("ld.acquire.gpu.u32 %0, [%1];" : "=r"(v) : "l"(p) : "memory");
    return v;
}
__device__ __forceinline__ void st_rel(unsigned* p, unsigned v) {
    asm volatile("st.release.gpu.u32 [%0], %1;" :: "l"(p), "r"(v) : "memory");
}

// ---------------------------------------------------------------------------
__global__ void reset_flags() {
    ((unsigned*)g_flag)[blockIdx.x * blockDim.x + threadIdx.x] = 0;
}

// ---------------------------------------------------------------------------
// Kernel A: xw[bt][h] = x[bt]·W_ih[h] + b_ih[h] + b_hh[h]  -> hidden region
// ---------------------------------------------------------------------------
__global__ void __launch_bounds__(256) xw_kernel(
    const float* __restrict__ x, const float* __restrict__ Wih,
    const float* __restrict__ bih, const float* __restrict__ bhh,
    float* __restrict__ hid_out)
{
    __shared__ float xs[64 * 65];
    __shared__ float ws[64 * 65];

    const int tid = threadIdx.x;
    const int hb  = blockIdx.x * 64;
    const int btb = blockIdx.y * 64;

    #pragma unroll
    for (int i = tid; i < 64 * 64; i += 256) {
        int r = i >> 6, c = i & 63;
        xs[r * 65 + c] = x[(btb + r) * 64 + c];
        ws[r * 65 + c] = Wih[(hb + r) * 64 + c];
    }
    __syncthreads();

    const int tx = tid & 15, ty = tid >> 4;
    float acc[4][4] = {};

    #pragma unroll 8
    for (int k = 0; k < 64; ++k) {
        float a0 = xs[(ty     ) * 65 + k];
        float a1 = xs[(ty + 16) * 65 + k];
        float a2 = xs[(ty + 32) * 65 + k];
        float a3 = xs[(ty + 48) * 65 + k];
        float b0 = ws[(tx     ) * 65 + k];
        float b1 = ws[(tx + 16) * 65 + k];
        float b2 = ws[(tx + 32) * 65 + k];
        float b3 = ws[(tx + 48) * 65 + k];
        acc[0][0] += a0 * b0; acc[0][1] += a0 * b1; acc[0][2] += a0 * b2; acc[0][3] += a0 * b3;
        acc[1][0] += a1 * b0; acc[1][1] += a1 * b1; acc[1][2] += a1 * b2; acc[1][3] += a1 * b3;
        acc[2][0] += a2 * b0; acc[2][1] += a2 * b1; acc[2][2] += a2 * b2; acc[2][3] += a2 * b3;
        acc[3][0] += a3 * b0; acc[3][1] += a3 * b1; acc[3][2] += a3 * b2; acc[3][3] += a3 * b3;
    }

    #pragma unroll
    for (int j = 0; j < 4; ++j) {
        int h = hb + tx + 16 * j;
        float bb = bih[h] + bhh[h];
        #pragma unroll
        for (int i = 0; i < 4; ++i) {
            int bt = btb + ty + 16 * i;
            hid_out[bt * H_ + h] = acc[i][j] + bb;
        }
    }
}

// ---------------------------------------------------------------------------
// Kernel B: persistent recurrence with broadcast-tiled warp GEMM.
// 128 blocks = 4 batch-groups(16) x 32 col-groups(32).
// Warp w: w4 = w&3 (K-chunk of 256), tile = w>>2 (col half: 16 cols).
// Lane (r = lane>>3, c = lane&7): 4 batches {4i+r} x 2 cols {tile*16+c+8j}.
// Per k-pair: 4 broadcast h loads + 2 broadcast w loads + 8 f2fma.
// Cross-warp K-reduction via 10KB Latin-square SMEM buffer.
// ---------------------------------------------------------------------------
__global__ void __launch_bounds__(TB, 1) rnn_recur(
    const float* __restrict__ hid_in,
    const float* __restrict__ Whh,
    float* __restrict__ out)
{
    extern __shared__ float sm[];
    float* wsm = sm;                    // 32 x HS  (~132.6 KB)
    float* hsm = sm + 32 * HS;          // 16 x HS  (~66.3 KB)
    float* red = sm + 48 * HS;          // 16*161 = 2576 floats (~10.3 KB)

    const int tid = threadIdx.x;
    const int bi  = blockIdx.x >> 5;
    const int ci  = blockIdx.x & 31;
    const int b0  = bi * 16;
    const int c0  = ci * 32;

    const int lane = tid & 31;
    const int w    = tid >> 5;
    const int w4   = w & 3;             // K-chunk id (256 floats)
    const int tile = w >> 2;            // col half
    const int r    = lane >> 3;         // batch subrow 0..3
    const int c    = lane & 7;          // col subcol 0..7

    // ---- stage W_hh slice once: rows c0..c0+31, row-major, stride HS ----
    const float2* W2 = (const float2*)Whh;
    #pragma unroll 4
    for (int i = tid; i < 32 * 512; i += TB) {
        int row = i >> 9, q = i & 511;
        *(float2*)&wsm[row * HS + 2 * q] = __ldg(&W2[(c0 + row) * 512 + q]);
    }

    const int koff = w4 * 256;          // this warp's K-chunk offset (floats)
    const float* hbp = hsm + r * HS + koff;
    const float* wbp = wsm + (tile * 16 + c) * HS + koff;

    float* hid_out = out + HID_OFF;
    float* hlast   = out + HL_OFF;

    // reduction/epilogue mapping: thread owns outputs (eb,ec) and (eb+8,ec)
    const int eb = tid >> 5;            // 0..7 (warp-uniform)
    const int ec = tid & 31;
    const int gb0 = b0 + eb, gb1 = b0 + eb + 8;
    const int gc  = c0 + ec;

    #pragma unroll 1
    for (int s = 0; s < T_; ++s) {
        // prefetch xw for this thread's two outputs (own locations)
        float xw0 = __ldcg(&hid_out[((size_t)gb0 * T_ + s) * H_ + gc]);
        float xw1 = __ldcg(&hid_out[((size_t)gb1 * T_ + s) * H_ + gc]);

        // ---- wait: warp 0 polls the 32 producer flags in parallel ----
        if (s > 0) {
            if (tid < 32)
                while ((int)(ld_acq(&g_flag[bi][tid][0]) - (unsigned)s) < 0) { }
            __syncthreads();
        }

        // ---- stage h slice (16 x 1024), row-major stride HS ----
        const float2* hsrc = (s == 0) ? (const float2*)hid_in
                                      : (const float2*)g_hbuf[(s - 1) & 1];
        #pragma unroll 8
        for (int t = 0; t < 32; ++t) {
            int i = t * 256 + tid;
            int row = i >> 9, q = i & 511;
            *(float2*)&hsm[row * HS + 2 * q] = __ldcg(&hsrc[(b0 + row) * 512 + q]);
        }
        __syncthreads();

        // ---- warp GEMM: 4x2 per lane over K-chunk 256 (broadcast loads) ----
        ull acc[4][2];
        #pragma unroll
        for (int i = 0; i < 4; ++i) { acc[i][0] = 0ull; acc[i][1] = 0ull; }

        #pragma unroll 4
        for (int k2 = 0; k2 < 128; ++k2) {
            ull hv[4], wv[2];
            #pragma unroll
            for (int i = 0; i < 4; ++i)
                hv[i] = *(const ull*)(hbp + 4 * i * HS + 2 * k2);
            wv[0] = *(const ull*)(wbp + 2 * k2);
            wv[1] = *(const ull*)(wbp + 8 * HS + 2 * k2);
            #pragma unroll
            for (int i = 0; i < 4; ++i) {
                acc[i][0] = f2fma(hv[i], wv[0], acc[i][0]);
                acc[i][1] = f2fma(hv[i], wv[1], acc[i][1]);
            }
        }

        // ---- write K-partials: red[batch*161 + col*5 + w4] ----
        #pragma unroll
        for (int i = 0; i < 4; ++i) {
            #pragma unroll
            for (int j = 0; j < 2; ++j) {
                int ob = 4 * i + r;
                int oc = tile * 16 + c + 8 * j;
                red[ob * RED_B + oc * RED_C + w4] = pairsum(acc[i][j]);
            }
        }
        __syncthreads();

        // ---- reduce 4 partials per output; 2 outputs per thread ----
        const int a0 = eb * RED_B + ec * RED_C;
        const int a1 = (eb + 8) * RED_B + ec * RED_C;
        float v0 = (red[a0] + red[a0 + 1]) + (red[a0 + 2] + red[a0 + 3]);
        float v1 = (red[a1] + red[a1 + 1]) + (red[a1 + 2] + red[a1 + 3]);

        float r0 = fmaxf(xw0 + v0, 0.0f);
        float r1 = fmaxf(xw1 + v1, 0.0f);

        hid_out[((size_t)gb0 * T_ + s) * H_ + gc] = r0;
        hid_out[((size_t)gb1 * T_ + s) * H_ + gc] = r1;
        float* hnew = g_hbuf[s & 1];
        hnew[gb0 * H_ + gc] = r0;
        hnew[gb1 * H_ + gc] = r1;
        if (s == T_ - 1) {
            hlast[gb0 * H_ + gc] = r0;
            hlast[gb1 * H_ + gc] = r1;
        }

        // ---- publish: all epilogues done, then release own flag ----
        if (s != T_ - 1) {
            __syncthreads();
            if (tid == 0)
                st_rel(&g_flag[bi][ci][0], (unsigned)(s + 1));
        }
    }
}

// ---------------------------------------------------------------------------
// Kernel C: output_list[bt][o] = hid[bt]·W_out[o] + b_out[o]   (f32x2)
// 64x64 tile, 256 threads, 4x4 f2 acc -> ~60 regs, 4 blocks/SM.
// ---------------------------------------------------------------------------
__global__ void __launch_bounds__(256) out_kernel(
    const float* __restrict__ hid, const float* __restrict__ Wout,
    const float* __restrict__ bout, float* __restrict__ outp)
{
    __shared__ float hs[64 * 34];
    __shared__ float ws2[64 * 34];

    const int tid = threadIdx.x;
    const int btb = blockIdx.x * 64;
    const int tx = tid & 15, ty = tid >> 4;

    const float2* hid2  = (const float2*)hid;
    const float2* wout2 = (const float2*)Wout;

    ull acc[4][4];
    #pragma unroll
    for (int i = 0; i < 4; ++i)
        #pragma unroll
        for (int j = 0; j < 4; ++j) acc[i][j] = 0ull;

    for (int kcb = 0; kcb < 512; kcb += 16) {
        #pragma unroll
        for (int i = tid; i < 64 * 16; i += 256) {
            int rr = i >> 4, q = i & 15;
            *(float2*)&hs[rr * 34 + q * 2]  = hid2[(btb + rr) * 512 + kcb + q];
            *(float2*)&ws2[rr * 34 + q * 2] = wout2[rr * 512 + kcb + q];
        }
        __syncthreads();

        #pragma unroll
        for (int k2 = 0; k2 < 16; ++k2) {
            ull a[4], b[4];
            #pragma unroll
            for (int i = 0; i < 4; ++i)
                a[i] = *(const ull*)&hs[(ty + 16 * i) * 34 + k2 * 2];
            #pragma unroll
            for (int j = 0; j < 4; ++j)
                b[j] = *(const ull*)&ws2[(tx + 16 * j) * 34 + k2 * 2];
            #pragma unroll
            for (int i = 0; i < 4; ++i)
                #pragma unroll
                for (int j = 0; j < 4; ++j)
                    acc[i][j] = f2fma(a[i], b[j], acc[i][j]);
        }
        __syncthreads();
    }

    #pragma unroll
    for (int j = 0; j < 4; ++j) {
        int o = tx + 16 * j;
        float bb = bout[o];
        #pragma unroll
        for (int i = 0; i < 4; ++i)
            outp[(btb + ty + 16 * i) * O_ + o] = pairsum(acc[i][j]) + bb;
    }
}

// ---------------------------------------------------------------------------
extern "C" void kernel_launch(void* const* d_in, const int* in_sizes, int n_in,
                              void* d_out, int out_size) {
    const float* x      = (const float*)d_in[0];
    const float* hidden = (const float*)d_in[1];
    const float* W_ih   = (const float*)d_in[2];
    const float* W_hh   = (const float*)d_in[3];
    const float* b_ih   = (const float*)d_in[4];
    const float* b_hh   = (const float*)d_in[5];
    const float* W_out  = (const float*)d_in[6];
    const float* b_out  = (const float*)d_in[7];
    float* out = (float*)d_out;

    reset_flags<<<16, 256>>>();

    dim3 gA(H_ / 64, (B_ * T_) / 64);
    xw_kernel<<<gA, 256>>>(x, W_ih, b_ih, b_hh, out + HID_OFF);

    // SMEM: 48*HS + 16*161 = 49728 + 2576 = 52304 floats = 209,216 B
    size_t smemB = (size_t)(48 * HS + 16 * RED_B) * sizeof(float);
    cudaFuncSetAttribute(rnn_recur, cudaFuncAttributeMaxDynamicSharedMemorySize,
                         (int)smemB);
    rnn_recur<<<NBLK, TB, smemB>>>(hidden, W_hh, out);

    out_kernel<<<(B_ * T_) / 64, 256>>>(out + HID_OFF, W_out, b_out, out + OUT_OFF);
}

// round 8
// speedup vs baseline: 1.5187x; 1.3265x over previous
#include <cuda_runtime.h>

// ---------------------------------------------------------------------------
// Elman RNN (relu), B=64, T=512, I=64, H=1024, O=64
// out = [ hidden_list (B,T,H) | output_list (B,T,O) | h_last (1,B,H) ]
// ---------------------------------------------------------------------------

#define B_   64
#define T_   512
#define I_   64
#define H_   1024
#define O_   64

#define HID_OFF  0
#define OUT_OFF  (B_ * T_ * H_)              // 33554432
#define HL_OFF   (OUT_OFF + B_ * T_ * O_)    // 35651584

#define NBLK 128        // persistent blocks (1/SM)
#define TB   256        // 2 warps / SMSP

// SMEM layout (floats): 32 K-chunks of 32 floats, each padded to 34
#define CH    34
#define HRow  1088      // 32 * 34

// scratch: h double buffer + per-(group,block) flags (128B stride)
__device__ float    g_hbuf[2][B_ * H_];
__device__ unsigned g_flag[4][32][32];

typedef unsigned long long ull;

__device__ __forceinline__ ull f2fma(ull a, ull b, ull c) {
    ull d;
    asm("fma.rn.f32x2 %0, %1, %2, %3;" : "=l"(d) : "l"(a), "l"(b), "l"(c));
    return d;
}
__device__ __forceinline__ float pairsum(ull a) {
    float lo = __uint_as_float((unsigned)(a & 0xffffffffull));
    float hi = __uint_as_float((unsigned)(a >> 32));
    return lo + hi;
}
__device__ __forceinline__ unsigned ld_acq(unsigned* p) {
    unsigned v;
    asm volatile("ld.acquire.gpu.u32 %0, [%1];" : "=r"(v) : "l"(p) : "memory");
    return v;
}
__device__ __forceinline__ void st_rel(unsigned* p, unsigned v) {
    asm volatile("st.release.gpu.u32 [%0], %1;" :: "l"(p), "r"(v) : "memory");
}

// ---------------------------------------------------------------------------
__global__ void reset_flags() {
    ((unsigned*)g_flag)[blockIdx.x * blockDim.x + threadIdx.x] = 0;
}

// ---------------------------------------------------------------------------
// Kernel A: xw[bt][h] = x[bt]·W_ih[h] + b_ih[h] + b_hh[h]  -> hidden region
// ---------------------------------------------------------------------------
__global__ void __launch_bounds__(256) xw_kernel(
    const float* __restrict__ x, const float* __restrict__ Wih,
    const float* __restrict__ bih, const float* __restrict__ bhh,
    float* __restrict__ hid_out)
{
    __shared__ float xs[64 * 65];
    __shared__ float ws[64 * 65];

    const int tid = threadIdx.x;
    const int hb  = blockIdx.x * 64;
    const int btb = blockIdx.y * 64;

    #pragma unroll
    for (int i = tid; i < 64 * 64; i += 256) {
        int r = i >> 6, c = i & 63;
        xs[r * 65 + c] = x[(btb + r) * 64 + c];
        ws[r * 65 + c] = Wih[(hb + r) * 64 + c];
    }
    __syncthreads();

    const int tx = tid & 15, ty = tid >> 4;
    float acc[4][4] = {};

    #pragma unroll 8
    for (int k = 0; k < 64; ++k) {
        float a0 = xs[(ty     ) * 65 + k];
        float a1 = xs[(ty + 16) * 65 + k];
        float a2 = xs[(ty + 32) * 65 + k];
        float a3 = xs[(ty + 48) * 65 + k];
        float b0 = ws[(tx     ) * 65 + k];
        float b1 = ws[(tx + 16) * 65 + k];
        float b2 = ws[(tx + 32) * 65 + k];
        float b3 = ws[(tx + 48) * 65 + k];
        acc[0][0] += a0 * b0; acc[0][1] += a0 * b1; acc[0][2] += a0 * b2; acc[0][3] += a0 * b3;
        acc[1][0] += a1 * b0; acc[1][1] += a1 * b1; acc[1][2] += a1 * b2; acc[1][3] += a1 * b3;
        acc[2][0] += a2 * b0; acc[2][1] += a2 * b1; acc[2][2] += a2 * b2; acc[2][3] += a2 * b3;
        acc[3][0] += a3 * b0; acc[3][1] += a3 * b1; acc[3][2] += a3 * b2; acc[3][3] += a3 * b3;
    }

    #pragma unroll
    for (int j = 0; j < 4; ++j) {
        int h = hb + tx + 16 * j;
        float bb = bih[h] + bhh[h];
        #pragma unroll
        for (int i = 0; i < 4; ++i) {
            int bt = btb + ty + 16 * i;
            hid_out[bt * H_ + h] = acc[i][j] + bb;
        }
    }
}

// ---------------------------------------------------------------------------
// Kernel B: persistent recurrence = R5 GEMM + flag sync + minimal barriers.
// 128 blocks = 4 batch-groups(16 batches) x 32 col-groups(32 cols).
// kc = tid&31 (lane, K-chunk of 32), p = tid>>5 (warp-uniform: pm batch
// octet, pn col octet). 8x8 f2fma tile -> butterfly shuffle reduction ->
// relu epilogue -> bar.arrive/sync -> st.release own flag.
// All warps poll all 32 flags (own flag >= s implies local FMA done ->
// no post-poll block barrier needed).
// ---------------------------------------------------------------------------
__global__ void __launch_bounds__(TB, 1) rnn_recur(
    const float* __restrict__ hid_in,
    const float* __restrict__ Whh,
    float* __restrict__ out)
{
    extern __shared__ float sm[];
    float* wsm = sm;                 // 32 rows x HRow  (~136 KB)
    float* hsm = sm + 32 * HRow;     // 16 rows x HRow  (~68 KB)

    const int tid = threadIdx.x;
    const int bi  = blockIdx.x >> 5;
    const int ci  = blockIdx.x & 31;
    const int b0  = bi * 16;
    const int c0  = ci * 32;

    const int lane = tid & 31;
    const int kc   = lane;             // K-chunk (lane-spanning)
    const int p    = tid >> 5;         // warp-uniform tile position 0..7
    const int pm   = p & 1;
    const int pn   = p >> 1;

    // ---- stage W_hh slice once: rows c0..c0+31, chunked layout ----
    const float2* W2 = (const float2*)Whh;
    #pragma unroll 4
    for (int i = tid; i < 32 * 512; i += TB) {
        int r = i >> 9, q = i & 511;
        *(float2*)&wsm[r * HRow + (q >> 4) * CH + (q & 15) * 2] =
            __ldg(&W2[(c0 + r) * 512 + q]);
    }

    const float* hb_ = hsm + pm * 8 * HRow + kc * CH;
    const float* wb_ = wsm + pn * 8 * HRow + kc * CH;

    float* hid_out = out + HID_OFF;
    float* hlast   = out + HL_OFF;

    // epilogue mapping (post-shuffle): lane holds outputs 2*lane, 2*lane+1 of
    // the warp's 64 = (batch pm*8 + (lane>>2), cols pn*8 + 2*(lane&3) + {0,1})
    const int gb = b0 + pm * 8 + (lane >> 2);
    const int gc = c0 + pn * 8 + 2 * (lane & 3);

    #pragma unroll 1
    for (int s = 0; s < T_; ++s) {
        // prefetch xw for this thread's two outputs (own location, safe early)
        float2 xw = *(const float2*)&hid_out[((size_t)gb * T_ + s) * H_ + gc];

        // ---- wait: every warp polls all 32 producer flags (lane -> flag) ----
        // Own flag >= s implies this block's epilogue barrier for step s-1
        // passed, so all local warps finished reading hsm -> safe to restage.
        if (s > 0) {
            while ((int)(ld_acq(&g_flag[bi][lane][0]) - (unsigned)s) < 0) { }
            __syncwarp();
        }

        // ---- stage h slice (16 x 1024): LDG.128 + paired STS.64 ----
        const float4* hsrc = (s == 0) ? (const float4*)hid_in
                                      : (const float4*)g_hbuf[(s - 1) & 1];
        #pragma unroll
        for (int t = 0; t < 16; ++t) {
            int i  = t * 256 + tid;
            int r  = i >> 8, f4 = i & 255;           // f4: float4 index in row
            float4 v = __ldcg(&hsrc[(b0 + r) * 256 + f4]);
            float* dst = &hsm[r * HRow + (f4 >> 3) * CH + (f4 & 7) * 4];
            *(float2*)dst       = make_float2(v.x, v.y);
            *(float2*)(dst + 2) = make_float2(v.z, v.w);
        }
        __syncthreads();

        // ---- 8x8 tile over private K-chunk of 32 ----
        ull acc[64];
        #pragma unroll
        for (int i = 0; i < 64; ++i) acc[i] = 0ull;

        #pragma unroll
        for (int k2 = 0; k2 < 16; ++k2) {
            ull hv[8];
            #pragma unroll
            for (int i = 0; i < 8; ++i)
                hv[i] = *(const ull*)(hb_ + i * HRow + k2 * 2);
            ull wv[4];
            #pragma unroll
            for (int j = 0; j < 4; ++j)
                wv[j] = *(const ull*)(wb_ + j * HRow + k2 * 2);
            #pragma unroll
            for (int i = 0; i < 8; ++i)
                #pragma unroll
                for (int j = 0; j < 4; ++j)
                    acc[i * 8 + j] = f2fma(hv[i], wv[j], acc[i * 8 + j]);
            #pragma unroll
            for (int j = 0; j < 4; ++j)
                wv[j] = *(const ull*)(wb_ + (j + 4) * HRow + k2 * 2);
            #pragma unroll
            for (int i = 0; i < 8; ++i)
                #pragma unroll
                for (int j = 0; j < 4; ++j)
                    acc[i * 8 + j + 4] = f2fma(hv[i], wv[j], acc[i * 8 + j + 4]);
        }

        // ---- pairsum then 5-round butterfly shuffle reduction ----
        float vals[64];
        #pragma unroll
        for (int v = 0; v < 64; ++v) vals[v] = pairsum(acc[v]);

        #pragma unroll
        for (int m = 16, cnt = 32; m >= 1; m >>= 1, cnt >>= 1) {
            bool up = (lane & m) != 0;
            #pragma unroll
            for (int i = 0; i < 32; ++i) {
                if (i >= cnt) break;
                float send = up ? vals[i] : vals[i + cnt];
                float keep = up ? vals[i + cnt] : vals[i];
                float recv = __shfl_xor_sync(0xffffffffu, send, m);
                vals[i] = keep + recv;
            }
        }
        // lane now holds vals[0], vals[1] = outputs 2*lane, 2*lane+1

        float2 rr;
        rr.x = fmaxf(xw.x + vals[0], 0.0f);
        rr.y = fmaxf(xw.y + vals[1], 0.0f);

        *(float2*)&hid_out[((size_t)gb * T_ + s) * H_ + gc] = rr;
        *(float2*)&g_hbuf[s & 1][gb * H_ + gc] = rr;
        if (s == T_ - 1)
            *(float2*)&hlast[gb * H_ + gc] = rr;

        // ---- epilogue rendezvous: warps 1..7 arrive, warp 0 syncs+releases
        if (s != T_ - 1) {
            if (p == 0) {
                asm volatile("bar.sync 1, %0;" :: "n"(TB) : "memory");
                if (tid == 0)
                    st_rel(&g_flag[bi][ci][0], (unsigned)(s + 1));
            } else {
                asm volatile("bar.arrive 1, %0;" :: "n"(TB) : "memory");
            }
        }
    }
}

// ---------------------------------------------------------------------------
// Kernel C: output_list[bt][o] = hid[bt]·W_out[o] + b_out[o]   (f32x2)
// 64x64 tile, 256 threads, 4x4 f2 acc.
// ---------------------------------------------------------------------------
__global__ void __launch_bounds__(256) out_kernel(
    const float* __restrict__ hid, const float* __restrict__ Wout,
    const float* __restrict__ bout, float* __restrict__ outp)
{
    __shared__ float hs[64 * 34];
    __shared__ float ws2[64 * 34];

    const int tid = threadIdx.x;
    const int btb = blockIdx.x * 64;
    const int tx = tid & 15, ty = tid >> 4;

    const float2* hid2  = (const float2*)hid;
    const float2* wout2 = (const float2*)Wout;

    ull acc[4][4];
    #pragma unroll
    for (int i = 0; i < 4; ++i)
        #pragma unroll
        for (int j = 0; j < 4; ++j) acc[i][j] = 0ull;

    for (int kcb = 0; kcb < 512; kcb += 16) {
        #pragma unroll
        for (int i = tid; i < 64 * 16; i += 256) {
            int rr = i >> 4, q = i & 15;
            *(float2*)&hs[rr * 34 + q * 2]  = hid2[(btb + rr) * 512 + kcb + q];
            *(float2*)&ws2[rr * 34 + q * 2] = wout2[rr * 512 + kcb + q];
        }
        __syncthreads();

        #pragma unroll
        for (int k2 = 0; k2 < 16; ++k2) {
            ull a[4], b[4];
            #pragma unroll
            for (int i = 0; i < 4; ++i)
                a[i] = *(const ull*)&hs[(ty + 16 * i) * 34 + k2 * 2];
            #pragma unroll
            for (int j = 0; j < 4; ++j)
                b[j] = *(const ull*)&ws2[(tx + 16 * j) * 34 + k2 * 2];
            #pragma unroll
            for (int i = 0; i < 4; ++i)
                #pragma unroll
                for (int j = 0; j < 4; ++j)
                    acc[i][j] = f2fma(a[i], b[j], acc[i][j]);
        }
        __syncthreads();
    }

    #pragma unroll
    for (int j = 0; j < 4; ++j) {
        int o = tx + 16 * j;
        float bb = bout[o];
        #pragma unroll
        for (int i = 0; i < 4; ++i)
            outp[(btb + ty + 16 * i) * O_ + o] = pairsum(acc[i][j]) + bb;
    }
}

// ---------------------------------------------------------------------------
extern "C" void kernel_launch(void* const* d_in, const int* in_sizes, int n_in,
                              void* d_out, int out_size) {
    const float* x      = (const float*)d_in[0];
    const float* hidden = (const float*)d_in[1];
    const float* W_ih   = (const float*)d_in[2];
    const float* W_hh   = (const float*)d_in[3];
    const float* b_ih   = (const float*)d_in[4];
    const float* b_hh   = (const float*)d_in[5];
    const float* W_out  = (const float*)d_in[6];
    const float* b_out  = (const float*)d_in[7];
    float* out = (float*)d_out;

    reset_flags<<<16, 256>>>();

    dim3 gA(H_ / 64, (B_ * T_) / 64);
    xw_kernel<<<gA, 256>>>(x, W_ih, b_ih, b_hh, out + HID_OFF);

    size_t smemB = (size_t)(48 * HRow) * sizeof(float);   // 208,896 B
    cudaFuncSetAttribute(rnn_recur, cudaFuncAttributeMaxDynamicSharedMemorySize,
                         (int)smemB);
    rnn_recur<<<NBLK, TB, smemB>>>(hidden, W_hh, out);

    out_kernel<<<(B_ * T_) / 64, 256>>>(out + HID_OFF, W_out, b_out, out + OUT_OFF);
}